// round 16
// baseline (speedup 1.0000x reference)
#include <cuda_runtime.h>
#include <cstdint>

// Problem constants
#define BATCH 32
#define CIN 8
#define COUT 8
#define DIN 16
#define DOUT 16
#define HW 1024            // 32*32
#define EPSV 1e-5f

// ---------------- scratch (device globals; no allocation allowed) ----------------
__device__ float g_pooled[BATCH*COUT*2*DOUT*HW];              // 33.5 MB [b][o][i][d][u][v]
__device__ float g_rbuf  [BATCH*COUT*DOUT*HW];                // 16.8 MB
__device__ float g_gate  [BATCH*COUT*DOUT*HW];                // 16.8 MB
__device__ float g_bnacc [16];
__device__ float g_bnAB  [16];

// ---------------- packed f32x2 helpers ----------------
typedef unsigned long long u64;
__device__ __forceinline__ u64 pk2(float lo, float hi){
    u64 r; asm("mov.b64 %0, {%1,%2};" : "=l"(r) : "f"(lo), "f"(hi)); return r;
}
__device__ __forceinline__ void upk2(u64 v, float& lo, float& hi){
    asm("mov.b64 {%0,%1}, %2;" : "=f"(lo), "=f"(hi) : "l"(v));
}
__device__ __forceinline__ u64 ffma2(u64 a, u64 b, u64 c){
    u64 d; asm("fma.rn.f32x2 %0, %1, %2, %3;" : "=l"(d) : "l"(a), "l"(b), "l"(c)); return d;
}
__device__ __forceinline__ u64 add2(u64 a, u64 b){
    u64 d; asm("add.rn.f32x2 %0, %1, %2;" : "=l"(d) : "l"(a), "l"(b)); return d;
}

// f32 -> tf32 (round to nearest)
__device__ __forceinline__ uint32_t f2tf32(float x){
    uint32_t r; asm("cvt.rna.tf32.f32 %0, %1;" : "=r"(r) : "f"(x)); return r;
}

#define MMA_TF32(acc, a, b) \
    asm volatile("mma.sync.aligned.m16n8k8.row.col.f32.tf32.tf32.f32 " \
                 "{%0,%1,%2,%3}, {%4,%5,%6,%7}, {%8,%9}, {%0,%1,%2,%3};" \
                 : "+f"((acc)[0]), "+f"((acc)[1]), "+f"((acc)[2]), "+f"((acc)[3]) \
                 : "r"((a)[0]), "r"((a)[1]), "r"((a)[2]), "r"((a)[3]), \
                   "r"((b)[0]), "r"((b)[1]))

// ---------------- K0: zero BN accumulators ----------------
__global__ void k0_zero(){
    if (threadIdx.x < 16) g_bnacc[threadIdx.x] = 0.f;
}
// dummies to steer ncu's capture slot onto k1_fused (4th launch gets profiled)
__global__ void kdummyA(){}
__global__ void kdummyB(){}

// ---------------- K1 (PERSISTENT, TF32, 2 CTAs/SM): conv2d GEMM + values/pool/routing ----------------
// CTA = (o, b); loops over 16 utiles of 2 u-rows. GEMM per utile: M=128 (m=c*16+d,
// gathered oc = c*128+o*16+d), N=64 positions, K=144. A staged ONCE (pair-packed tf32),
// B restaged per utile. Pair-packed layout: per 8-k block, slot s in 0..3 holds
// (k=8blk+s, k=8blk+s+4) as u64; slot XOR'd by (row&3) -> LDS.64 frag loads are
// uniformly 2-way (the 8B/lane minimum). Warps 4(m) x 2(n), per step 8 LDS.64 + 8 MMA.
// Epilogue: votes->smem over B region; spill-free c-major einsum + pool + routing.
#define K1_PAIRS 74                          // u64 per row (72 data + 2 pad)
#define K1_SM_A   0                          // 128*74*8 = 75776
#define K1_SM_B   75776                      // 64*74*8 = 37888
#define K1_SMEM   113664

__global__ __launch_bounds__(256, 2) void k1_fused(
        const float* __restrict__ caps, const float* __restrict__ Wt,
        const float* __restrict__ bt,   const float* __restrict__ Wv,
        const float* __restrict__ bv){
    extern __shared__ __align__(16) char smem[];
    __shared__ __align__(16) u64 sWvP[128];   // [(c*8+co)*2 + k1] = (Wv[co+16k1][c], Wv[co+16k1+8][c])
    __shared__ __align__(16) u64 sBvP[16];    // [co*2 + k1]
    uint32_t* sA = (uint32_t*)(smem + K1_SM_A);
    uint32_t* sB = (uint32_t*)(smem + K1_SM_B);
    float* votes_s = (float*)(smem + K1_SM_B);   // aliases B after MMA (sync-guarded)

    int o   = blockIdx.x;                // 0..7
    int b   = blockIdx.y;                // 0..31
    int tid = threadIdx.x;
    int wid = tid >> 5;
    int lane = tid & 31;

    // ---- stage Wv pairs / bv pairs ----
    if (tid < 128){
        int c = tid >> 4, rem = tid & 15;
        int co = rem >> 1, k1 = rem & 1;
        int ma = co + 16*k1;
        sWvP[tid] = pk2(Wv[o*256 + ma*8 + c], Wv[o*256 + (ma+8)*8 + c]);
    }
    if (tid < 16){
        int co = tid >> 1, k1 = tid & 1;
        sBvP[tid] = pk2(bv[o*32 + co + 16*k1], bv[o*32 + co + 16*k1 + 8]);
    }

    // ---- stage A once: gathered W rows -> tf32 pair-packed ----
    for (int it = 0; it < 36; it++){
        int i2 = tid + it*256;           // over 128*72 float2
        int m  = i2 / 72, k2 = i2 - m*72;
        int ocg = ((m >> 4) * 128) + o*16 + (m & 15);
        float2 w = ((const float2*)(Wt + (size_t)ocg*144))[k2];
        int k0 = 2*k2;
        int mx4 = m & 3;
        #pragma unroll
        for (int e = 0; e < 2; e++){
            int k = k0 + e;
            int blk = k >> 3, r = k & 7;
            int addr = m*(K1_PAIRS*2) + blk*8 + (((r & 3) ^ mx4) << 1) + (r >> 2);
            sA[addr] = f2tf32(e ? w.y : w.x);
        }
    }

    // ---- warp/frag constants ----
    int wm = wid & 3;        // m-block of 32 rows
    int wn = wid >> 2;       // n-block of 32 cols
    int g = lane >> 2, t = lane & 3;
    int tx = t ^ (g & 3);

    const uint2* pAlo[2];
    const uint2* pAhi[2];
    #pragma unroll
    for (int mf = 0; mf < 2; mf++){
        int row0 = wm*32 + mf*16 + g;
        pAlo[mf] = (const uint2*)(sA) + row0*K1_PAIRS + tx;
        pAhi[mf] = (const uint2*)(sA) + (row0+8)*K1_PAIRS + tx;
    }
    const uint2* pB[4];
    #pragma unroll
    for (int nf = 0; nf < 4; nf++){
        int row = wn*32 + nf*8 + g;
        pB[nf] = (const uint2*)(sB) + row*K1_PAIRS + tx;
    }

    // bias values (constant across utiles)
    float bias0v[2], bias1v[2];
    #pragma unroll
    for (int mf = 0; mf < 2; mf++){
        int m0 = wm*32 + mf*16 + g;
        int m1 = m0 + 8;
        bias0v[mf] = __ldg(bt + ((m0 >> 4)*8 + o)*16 + (m0 & 15));
        bias1v[mf] = __ldg(bt + ((m1 >> 4)*8 + o)*16 + (m1 & 15));
    }

    int pos  = tid & 63;
    int dgrp = tid >> 6;
    size_t obase = (size_t)(b*8 + o);
    const float* cb = caps + (size_t)b * (DIN*HW);

    // ================== persistent loop over utiles ==================
    for (int ut = 0; ut < 16; ut++){
        int u0 = ut*2;

        __syncthreads();   // prev epilogue reads of votes_s / A staging done

        // ---- stage B (im2col, tf32, pair-packed) ----
        for (int it = 0; it < 36; it++){
            int idx = tid + it*256;          // idx = k*64 + n
            int n = idx & 63, k = idx >> 6;
            int din = k / 9, tap = k - 9*din;
            int ky = tap / 3, kx = tap - 3*ky;
            int u = u0 + (n >> 5) + ky - 1;
            int v = (n & 31) + kx - 1;
            float x = 0.f;
            if ((unsigned)u < 32u && (unsigned)v < 32u) x = cb[din*HW + (u << 5) + v];
            int blk = k >> 3, r = k & 7;
            int addr = n*(K1_PAIRS*2) + blk*8 + (((r & 3) ^ (n & 3)) << 1) + (r >> 2);
            sB[addr] = f2tf32(x);
        }
        __syncthreads();

        // ---- TF32 MMA mainloop ----
        float acc[2][4][4];
        #pragma unroll
        for (int mf = 0; mf < 2; mf++)
            #pragma unroll
            for (int nf = 0; nf < 4; nf++)
                #pragma unroll
                for (int r = 0; r < 4; r++) acc[mf][nf][r] = 0.f;

        #pragma unroll
        for (int step = 0; step < 18; step++){
            uint32_t a[2][4];
            uint32_t bb[4][2];
            #pragma unroll
            for (int mf = 0; mf < 2; mf++){
                uint2 lo = pAlo[mf][step*4];
                uint2 hi = pAhi[mf][step*4];
                a[mf][0] = lo.x; a[mf][1] = hi.x; a[mf][2] = lo.y; a[mf][3] = hi.y;
            }
            #pragma unroll
            for (int nf = 0; nf < 4; nf++){
                uint2 bv2 = pB[nf][step*4];
                bb[nf][0] = bv2.x; bb[nf][1] = bv2.y;
            }
            #pragma unroll
            for (int mf = 0; mf < 2; mf++)
                #pragma unroll
                for (int nf = 0; nf < 4; nf++)
                    MMA_TF32(acc[mf][nf], a[mf], bb[nf]);
        }

        __syncthreads();   // MMA reads of B done before votes overwrite

        // ---- votes -> smem [n 64][m stride 129] (over B region) ----
        #pragma unroll
        for (int mf = 0; mf < 2; mf++){
            int m0 = wm*32 + mf*16 + g;
            int m1 = m0 + 8;
            #pragma unroll
            for (int nf = 0; nf < 4; nf++){
                int n0 = wn*32 + nf*8 + 2*t;
                votes_s[(n0  )*129 + m0] = acc[mf][nf][0] + bias0v[mf];
                votes_s[(n0+1)*129 + m0] = acc[mf][nf][1] + bias0v[mf];
                votes_s[(n0  )*129 + m1] = acc[mf][nf][2] + bias1v[mf];
                votes_s[(n0+1)*129 + m1] = acc[mf][nf][3] + bias1v[mf];
            }
        }
        __syncthreads();

        // ---- fused K2: spill-free values einsum + pool + routing ----
        {
            float* pool0 = g_pooled + obase*2*(DOUT*HW) + ut*64 + pos;
            float* rb    = g_rbuf   + obase  *(DOUT*HW) + ut*64 + pos;
            const float* vrow = votes_s + pos*129;

            #pragma unroll 1
            for (int j = 0; j < 4; j++){
                int d = dgrp + 4*j;
                u64 x[8];
                #pragma unroll
                for (int c = 0; c < 8; c++){
                    float vcv = vrow[c*16 + d];
                    x[c] = pk2(vcv, vcv);
                }
                float mx = -3.0e38f;
                u64 sumP = pk2(0.f, 0.f);
                float rnum = 0.f, rden = 0.f;
                #pragma unroll
                for (int co = 0; co < 8; co++){
                    u64 a0 = sBvP[2*co], a1 = sBvP[2*co+1];
                    #pragma unroll
                    for (int c = 0; c < 8; c++){
                        a0 = ffma2(sWvP[(c*8+co)*2    ], x[c], a0);
                        a1 = ffma2(sWvP[(c*8+co)*2 + 1], x[c], a1);
                    }
                    float v0,v1,v2,v3;
                    upk2(a0, v0, v1);   // val[co], val[co+8]
                    upk2(a1, v2, v3);   // val[co+16], val[co+24]
                    mx = fmaxf(mx, fmaxf(fmaxf(v0,v1), fmaxf(v2,v3)));
                    sumP = add2(sumP, add2(a0, a1));
                    float s1 = (v0+v1)+(v2+v3);
                    float s2 = v0*v0 + v1*v1 + v2*v2 + v3*v3;
                    float mu = s1*0.25f;
                    float var = fmaxf(s2*0.25f - mu*mu, 1e-37f);
                    float w = rsqrtf(var);
                    rden += w;
                    rnum += w*mu;
                }
                float slo, shi; upk2(sumP, slo, shi);
                pool0[d*1024]            = mx;
                pool0[DOUT*HW + d*1024]  = (slo + shi) * (1.f/32.f);
                rb[d*1024] = rnum / rden;
            }
        }
    }
}

// ---------------- K3: conv3d gate + BN partial sums ----------------
#define K3_T (2*18*10*34)
__global__ __launch_bounds__(256) void k3_conv3d(const float* __restrict__ Ws){
    extern __shared__ float sT[];
    __shared__ float sWs[54];
    __shared__ float sred[16];
    int ut = blockIdx.x, o = blockIdx.y, b = blockIdx.z;
    int tid = threadIdx.x;
    if (tid < 54) sWs[tid] = Ws[tid];
    const float* pb = g_pooled + (size_t)(b*8 + o)*2*(DOUT*HW);
    int u0 = ut*8;
    for (int idx = tid; idx < K3_T; idx += 256){
        int vx = idx % 34; int r1 = idx / 34;
        int uy = r1 % 10;  int r2 = r1 / 10;
        int dz = r2 % 18;  int i  = r2 / 18;
        int d = dz - 1, u = u0 + uy - 1, v = vx - 1;
        float x = 0.f;
        if ((unsigned)d < 16u && (unsigned)u < 32u && (unsigned)v < 32u)
            x = pb[i*(DOUT*HW) + d*HW + u*32 + v];
        sT[idx] = x;
    }
    __syncthreads();

    int ul = tid >> 5, v = tid & 31;
    float acc[16];
    #pragma unroll
    for (int dI = 0; dI < 16; dI++) acc[dI] = 0.f;

    #pragma unroll
    for (int dd = 0; dd < 18; dd++){
        float t[18];
        #pragma unroll
        for (int i = 0; i < 2; i++)
            #pragma unroll
            for (int dy = 0; dy < 3; dy++)
                #pragma unroll
                for (int dx = 0; dx < 3; dx++)
                    t[i*9 + dy*3 + dx] = sT[((i*18 + dd)*10 + ul + dy)*34 + v + dx];
        #pragma unroll
        for (int dz = 0; dz < 3; dz++){
            int dO = dd - dz;
            if (dO >= 0 && dO < 16){
                float a = acc[dO];
                #pragma unroll
                for (int i = 0; i < 2; i++)
                    #pragma unroll
                    for (int dy = 0; dy < 3; dy++)
                        #pragma unroll
                        for (int dx = 0; dx < 3; dx++)
                            a += t[i*9 + dy*3 + dx] * sWs[(i*3 + dz)*9 + dy*3 + dx];
                acc[dO] = a;
            }
        }
    }

    float s = 0.f, q = 0.f;
    float* gb = g_gate + (size_t)(b*8 + o)*(DOUT*HW) + (u0 + ul)*32 + v;
    #pragma unroll
    for (int dI = 0; dI < 16; dI++){
        gb[dI*HW] = acc[dI];
        s += acc[dI]; q += acc[dI]*acc[dI];
    }
    #pragma unroll
    for (int off = 16; off; off >>= 1){
        s += __shfl_xor_sync(0xffffffffu, s, off);
        q += __shfl_xor_sync(0xffffffffu, q, off);
    }
    if ((tid & 31) == 0){ sred[tid>>5] = s; sred[8 + (tid>>5)] = q; }
    __syncthreads();
    if (tid == 0){
        float S = 0.f, Q = 0.f;
        for (int i = 0; i < 8; i++){ S += sred[i]; Q += sred[8+i]; }
        atomicAdd(&g_bnacc[o],     S);
        atomicAdd(&g_bnacc[8 + o], Q);
    }
}

// ---------------- K4: finalize BN affine ----------------
__global__ void k4_bn(const float* __restrict__ bng, const float* __restrict__ bnb){
    int o = threadIdx.x;
    if (o < 8){
        const float n = (float)(BATCH*DOUT*HW);
        float mu  = g_bnacc[o] / n;
        float var = g_bnacc[8+o] / n - mu*mu;
        float A = bng[0] / sqrtf(var + EPSV);
        g_bnAB[o]     = A;
        g_bnAB[8 + o] = bnb[0] - mu*A;
    }
}

// ---------------- K5: gate*routing + LayerNorm + transposed write ----------------
__global__ __launch_bounds__(256) void k5_final(
        const float* __restrict__ lng, const float* __restrict__ lnb,
        float* __restrict__ out){
    extern __shared__ float scn[];
    __shared__ float sred[16];
    __shared__ float sMV[2];
    int b = blockIdx.x, o = blockIdx.y;
    int tid = threadIdx.x;
    float A = g_bnAB[o], Bb = g_bnAB[8 + o];
    const float* gg = g_gate + (size_t)(b*8 + o)*16384;
    const float* rr = g_rbuf + (size_t)(b*8 + o)*16384;
    float s = 0.f, q = 0.f;
    #pragma unroll 8
    for (int j = 0; j < 64; j++){
        int p = tid + j*256;
        float gn = gg[p]*A + Bb;
        float sc = 1.f + 1.f/(1.f + expf(-gn));
        float cn = rr[p] * sc;
        scn[p] = cn; s += cn; q += cn*cn;
    }
    #pragma unroll
    for (int off = 16; off; off >>= 1){
        s += __shfl_xor_sync(0xffffffffu, s, off);
        q += __shfl_xor_sync(0xffffffffu, q, off);
    }
    if ((tid & 31) == 0){ sred[tid>>5] = s; sred[8 + (tid>>5)] = q; }
    __syncthreads();
    if (tid == 0){
        float S = 0.f, Q = 0.f;
        for (int i = 0; i < 8; i++){ S += sred[i]; Q += sred[8+i]; }
        float mean = S * (1.f/16384.f);
        float var  = Q * (1.f/16384.f) - mean*mean;
        sMV[0] = mean;
        sMV[1] = 1.f / sqrtf(var + EPSV);
    }
    __syncthreads();
    float mean = sMV[0], inv = sMV[1];
    float* ob = out + ((size_t)o*BATCH + b)*16384;
    #pragma unroll 8
    for (int j = 0; j < 64; j++){
        int p = tid + j*256;
        ob[p] = (scn[p] - mean)*inv*lng[p] + lnb[p];
    }
}

// ---------------- launch ----------------
extern "C" void kernel_launch(void* const* d_in, const int* in_sizes, int n_in,
                              void* d_out, int out_size){
    const float *caps=0,*Wt=0,*bt=0,*Wv=0,*bv=0,*Ws=0,*bng=0,*bnb=0,*lng=0,*lnb=0;
    int seen1 = 0, seen16k = 0;
    for (int i = 0; i < n_in; i++){
        const float* p = (const float*)d_in[i];
        switch (in_sizes[i]){
            case 524288: caps = p; break;
            case 147456: Wt = p; break;
            case 1024:   bt = p; break;
            case 2048:   Wv = p; break;
            case 256:    bv = p; break;
            case 54:     Ws = p; break;
            case 1:      if (!seen1){ bng = p; seen1 = 1; } else bnb = p; break;
            case 16384:  if (!seen16k){ lng = p; seen16k = 1; } else lnb = p; break;
            default: break;
        }
    }
    float* out = (float*)d_out;

    cudaFuncSetAttribute(k1_fused,  cudaFuncAttributeMaxDynamicSharedMemorySize, K1_SMEM);
    cudaFuncSetAttribute(k3_conv3d, cudaFuncAttributeMaxDynamicSharedMemorySize, K3_T*4);
    cudaFuncSetAttribute(k5_final,  cudaFuncAttributeMaxDynamicSharedMemorySize, 16384*4);

    k0_zero<<<1, 32>>>();
    kdummyA<<<1, 32>>>();                                   // steer ncu slot
    kdummyB<<<1, 32>>>();                                   // steer ncu slot
    k1_fused<<<dim3(8, 32), 256, K1_SMEM>>>(caps, Wt, bt, Wv, bv);
    k3_conv3d<<<dim3(4, 8, 32), 256, K3_T*4>>>(Ws);
    k4_bn<<<1, 32>>>(bng, bnb);
    k5_final<<<dim3(32, 8), 256, 16384*4>>>(lng, lnb, out);
}